// round 8
// baseline (speedup 1.0000x reference)
#include <cuda_runtime.h>
#include <math.h>

// Fixed problem shapes
#define DIM   32
#define NN    32          // neighbors per entity
#define NRELS 64
#define RP    33          // padded pitch for rel table in smem
#define TPB   1024        // 32 warps = 32 hop-1 nodes per batch element

__device__ __forceinline__ float wmax(float v) {
#pragma unroll
    for (int o = 16; o; o >>= 1) v = fmaxf(v, __shfl_xor_sync(0xffffffffu, v, o));
    return v;
}
__device__ __forceinline__ float wsum(float v) {
#pragma unroll
    for (int o = 16; o; o >>= 1) v += __shfl_xor_sync(0xffffffffu, v, o);
    return v;
}

// dot(self_vec_in_smem, rel_row) with float4 broadcast of the self vector:
// 8 LDS.128 broadcasts (8 wavefronts) + 32 scalar rel reads.
__device__ __forceinline__ float score_dot(const float* __restrict__ svb,
                                           const float* __restrict__ rel_s,
                                           int rr) {
    const float4* sv4 = (const float4*)svb;
    const float*  rp  = &rel_s[rr * RP];
    float s = 0.f;
#pragma unroll
    for (int q = 0; q < 8; q++) {
        const float4 v = sv4[q];
        s += v.x * rp[4*q+0] + v.y * rp[4*q+1] + v.z * rp[4*q+2] + v.w * rp[4*q+3];
    }
    return s;
}

// GEMV row: o = b + sum_d h[d] * W[d][lane]; h broadcast as float4.
__device__ __forceinline__ float gemv_col(const float* __restrict__ svb,
                                          const float* __restrict__ W_s,
                                          float bias_j, int lane) {
    const float4* sv4 = (const float4*)svb;
    float o = bias_j;
#pragma unroll
    for (int q = 0; q < 8; q++) {
        const float4 v = sv4[q];
        o += v.x * W_s[(4*q+0) * DIM + lane];
        o += v.y * W_s[(4*q+1) * DIM + lane];
        o += v.z * W_s[(4*q+2) * DIM + lane];
        o += v.w * W_s[(4*q+3) * DIM + lane];
    }
    return o;
}

// weighted aggregate: a = sum_n sc[n] * src[en[n]*DIM + lane]
// sc/en broadcast as float4/int4 (8+8 wavefronts), 32 gathers.
__device__ __forceinline__ float agg_gather(const float* __restrict__ scb,
                                            const int* __restrict__ enb,
                                            const float* __restrict__ src,
                                            int lane) {
    const float4* sc4 = (const float4*)scb;
    const int4*   en4 = (const int4*)enb;
    float a = 0.f;
#pragma unroll
    for (int q = 0; q < 8; q++) {
        const float4 sc = sc4[q];
        const int4   e  = en4[q];
        a += sc.x * src[e.x * DIM + lane];
        a += sc.y * src[e.y * DIM + lane];
        a += sc.z * src[e.z * DIM + lane];
        a += sc.w * src[e.w * DIM + lane];
    }
    return a;
}

// ---------------------------------------------------------------------------
// Fused KGCN: one block per batch element.
//   Phase A (32 warps): hop-1 nodes m=0..31 -> out1 (smem); warp 0 also hop-0 v0.
//   Phase B (warp 0): iteration 1 over out1 -> final output.
// ---------------------------------------------------------------------------
__global__ __launch_bounds__(TPB, 2)
void kgcn_fused_kernel(const int* __restrict__ drug,
                       const int* __restrict__ adj_e,
                       const int* __restrict__ adj_r,
                       const float* __restrict__ ent,
                       const float* __restrict__ rel,
                       const float* __restrict__ W,
                       const float* __restrict__ bias,
                       float* __restrict__ out)
{
    __shared__ float rel_s[NRELS * RP];
    __shared__ float W_s[DIM * DIM];        // W_s[d][j]
    __shared__ float b_s[DIM];
    __shared__ float out1[NN * DIM];        // hop-1 results
    __shared__ float v0_s[DIM];
    __shared__ float sv_s[32][32];          // per-warp self vector (rows 128B aligned)
    __shared__ float sc_s[32][32];          // per-warp softmax scores
    __shared__ int   en_s[32][32];          // per-warp neighbor ids

    const int tid  = threadIdx.x;
    const int lane = tid & 31;
    const int w    = tid >> 5;              // warp id == hop-1 node index m

    for (int i = tid; i < NRELS * DIM; i += TPB)
        rel_s[(i >> 5) * RP + (i & 31)] = rel[i];
    for (int i = tid; i < DIM * DIM; i += TPB) W_s[i] = W[i];
    if (tid < DIM) b_s[tid] = bias[tid];
    __syncthreads();

    const int b  = blockIdx.x;
    const int e0 = drug[b];

    float* svb = sv_s[w];
    float* scb = sc_s[w];
    int*   enb = en_s[w];

    // =================== Phase A: hop-1 node m = w ===================
    {
        const int e1 = adj_e[e0 * NN + w];

        const float sv = ent[e1 * DIM + lane];       // coalesced row
        const int   en = adj_e[e1 * NN + lane];      // lane = neighbor n
        const int   rr = adj_r[e1 * NN + lane];

        svb[lane] = sv;
        enb[lane] = en;
        __syncwarp();

        float s = score_dot(svb, rel_s, rr);

        const float mx = wmax(s);
        const float ex = __expf(s - mx);
        const float sm = wsum(ex);
        scb[lane] = ex / sm;
        __syncwarp();

        const float a = agg_gather(scb, enb, ent, lane);

        const float h = sv + a;
        __syncwarp();
        svb[lane] = h;
        __syncwarp();

        const float o = gemv_col(svb, W_s, b_s[lane], lane);
        out1[w * DIM + lane] = 1.f / (1.f + __expf(-o));   // sigmoid
    }

    // ---- warp 0 also computes hop-0 v0 (independent of hop-1 results) ----
    if (w == 0) {
        const float sv = ent[e0 * DIM + lane];
        const int   en = adj_e[e0 * NN + lane];
        const int   rr = adj_r[e0 * NN + lane];

        __syncwarp();
        svb[lane] = sv;
        enb[lane] = en;
        __syncwarp();

        float s = score_dot(svb, rel_s, rr);

        const float mx = wmax(s);
        const float ex = __expf(s - mx);
        const float sm = wsum(ex);
        scb[lane] = ex / sm;
        __syncwarp();

        const float a = agg_gather(scb, enb, ent, lane);

        const float h = sv + a;
        __syncwarp();
        svb[lane] = h;
        __syncwarp();

        const float o = gemv_col(svb, W_s, b_s[lane], lane);
        v0_s[lane] = 1.f / (1.f + __expf(-o));
    }

    __syncthreads();

    // =================== Phase B: iteration 1 (warp 0) ===================
    if (w == 0) {
        const float v0 = v0_s[lane];
        const int   rr = adj_r[e0 * NN + lane];      // same relation rows as hop-0

        __syncwarp();
        svb[lane] = v0;
        __syncwarp();

        float s = score_dot(svb, rel_s, rr);

        const float mx = wmax(s);
        const float ex = __expf(s - mx);
        const float sm = wsum(ex);
        scb[lane] = ex / sm;
        __syncwarp();

        // neighbors are the hop-1 outputs in shared memory (coalesced LDS rows)
        const float4* sc4 = (const float4*)scb;
        float a = 0.f;
#pragma unroll
        for (int q = 0; q < 8; q++) {
            const float4 sc = sc4[q];
            a += sc.x * out1[(4*q+0) * DIM + lane];
            a += sc.y * out1[(4*q+1) * DIM + lane];
            a += sc.z * out1[(4*q+2) * DIM + lane];
            a += sc.w * out1[(4*q+3) * DIM + lane];
        }

        const float h = v0 + a;
        __syncwarp();
        svb[lane] = h;
        __syncwarp();

        const float o = gemv_col(svb, W_s, b_s[lane], lane);
        out[b * DIM + lane] = tanhf(o);
    }
}

extern "C" void kernel_launch(void* const* d_in, const int* in_sizes, int n_in,
                              void* d_out, int out_size)
{
    const int*   drug  = (const int*)  d_in[0];  // [B]
    const int*   adj_e = (const int*)  d_in[1];  // [NUM_ENT, 32]
    const int*   adj_r = (const int*)  d_in[2];  // [NUM_ENT, 32]
    const float* ent   = (const float*)d_in[3];  // [NUM_ENT, 32]
    const float* rel   = (const float*)d_in[4];  // [64, 32]
    const float* W     = (const float*)d_in[5];  // [32, 32]
    const float* bias  = (const float*)d_in[6];  // [32]
    float* out = (float*)d_out;

    const int B = in_sizes[0];
    kgcn_fused_kernel<<<B, TPB>>>(drug, adj_e, adj_r, ent, rel, W, bias, out);
}